// round 1
// baseline (speedup 1.0000x reference)
#include <cuda_runtime.h>
#include <cstdint>

#define N_MAX 25000
#define E_MAX 400000
#define CCH 64

static __device__ float4 d_h[N_MAX * CCH];   // node features [N][C][4] (h0, h1x, h1y, h1z)
static __device__ float4 d_x[N_MAX * CCH];   // up-projected  [N][C][4]
static __device__ float4 d_M[N_MAX * CCH];   // scatter accum [N][C][4]
static __device__ float  d_ef[E_MAX * 8];    // edge bessel feats
static __device__ float4 d_Y[E_MAX];         // sqrt3 * unit vec (w unused)

__device__ __forceinline__ float silu_f(float v) {
    return v / (1.0f + __expf(-v));
}

__device__ __forceinline__ unsigned long long pack2(float x) {
    unsigned long long r;
    asm("mov.b64 %0, {%1, %1};" : "=l"(r) : "f"(x));
    return r;
}
__device__ __forceinline__ void fma2(unsigned long long &d, unsigned long long a, unsigned long long b) {
    asm("fma.rn.f32x2 %0, %1, %2, %0;" : "+l"(d) : "l"(a), "l"(b));
}
__device__ __forceinline__ float2 unpack2(unsigned long long v) {
    float2 r;
    asm("mov.b64 {%0, %1}, %2;" : "=f"(r.x), "=f"(r.y) : "l"(v));
    return r;
}

// ---------------------------------------------------------------------------
// Per-edge geometry: Y1 = sqrt3 * unit vec, bessel radial feats * poly cutoff
// ---------------------------------------------------------------------------
__global__ void k_geom(const float* __restrict__ pos, const int* __restrict__ ei, int E_) {
    int e = blockIdx.x * blockDim.x + threadIdx.x;
    if (e >= E_) return;
    int s = ei[e];
    int r_ = ei[E_ + e];
    float vx = pos[3*s + 0] - pos[3*r_ + 0];
    float vy = pos[3*s + 1] - pos[3*r_ + 1];
    float vz = pos[3*s + 2] - pos[3*r_ + 2];
    float rr = sqrtf(vx*vx + vy*vy + vz*vz);
    rr = fmaxf(rr, 1e-6f);
    float inv_r = 1.0f / rr;
    const float SQRT3 = 1.7320508075688772f;
    float4 Y;
    Y.x = SQRT3 * vx * inv_r;
    Y.y = SQRT3 * vy * inv_r;
    Y.z = SQRT3 * vz * inv_r;
    Y.w = 0.0f;
    d_Y[e] = Y;
    // poly cutoff p=6: 1 - 28x^6 + 48x^7 - 21x^8 for x<1, else 0
    float x = rr * 0.2f;
    float x2 = x * x;
    float x6 = x2 * x2 * x2;
    float fc = 1.0f - 28.0f*x6 + 48.0f*x6*x - 21.0f*x6*x2;
    fc = (x < 1.0f) ? fc : 0.0f;
    const float BC = 0.6324555320336759f;      // sqrt(2/5)
    const float PI_O_R = 0.6283185307179586f;  // pi/5
    float pref = BC * inv_r * fc;
    float ef[8];
    #pragma unroll
    for (int k = 0; k < 8; k++)
        ef[k] = pref * sinf((float)(k + 1) * PI_O_R * rr);
    float4* dst = (float4*)(d_ef + (size_t)e * 8);
    dst[0] = make_float4(ef[0], ef[1], ef[2], ef[3]);
    dst[1] = make_float4(ef[4], ef[5], ef[6], ef[7]);
}

// ---------------------------------------------------------------------------
// h0 init from embedding (one-hot @ W == row select); h1 = 0
// ---------------------------------------------------------------------------
__global__ void k_embed(const int* __restrict__ species, const float* __restrict__ embW, int N_) {
    int idx = blockIdx.x * blockDim.x + threadIdx.x;
    if (idx >= N_ * CCH) return;
    int n = idx >> 6, c = idx & 63;
    int sp = species[n];
    d_h[idx] = make_float4(embW[sp * CCH + c], 0.0f, 0.0f, 0.0f);
}

// ---------------------------------------------------------------------------
// Up-projection: x0 = h0 @ W0, x1 = channel-mix(h1, W1); also zeroes d_M
// ---------------------------------------------------------------------------
__global__ void __launch_bounds__(256) k_nodeup(const float* __restrict__ W0g,
                                                const float* __restrict__ W1g, int N_) {
    __shared__ float sW0[4096];
    __shared__ float sW1[4096];
    __shared__ float4 sH[4 * CCH];
    int tid = threadIdx.x;
    for (int i = tid; i < 4096; i += 256) { sW0[i] = W0g[i]; sW1[i] = W1g[i]; }
    __syncthreads();
    int base = blockIdx.x * 64;
    int c = tid & 63, sub = tid >> 6;
    for (int g = 0; g < 16; g++) {
        int n = base + g * 4 + sub;
        bool act = n < N_;
        if (act) sH[sub * CCH + c] = d_h[(size_t)n * CCH + c];
        __syncthreads();
        if (act) {
            float ax = 0, ay = 0, az = 0, aw = 0;
            const float4* hr = &sH[sub * CCH];
            #pragma unroll 8
            for (int cc = 0; cc < 64; cc++) {
                float4 hv = hr[cc];
                float w0 = sW0[cc * 64 + c];
                float w1 = sW1[cc * 64 + c];
                ax += hv.x * w0;
                ay += hv.y * w1;
                az += hv.z * w1;
                aw += hv.w * w1;
            }
            d_x[(size_t)n * CCH + c] = make_float4(ax, ay, az, aw);
            d_M[(size_t)n * CCH + c] = make_float4(0, 0, 0, 0);
        }
        __syncthreads();
    }
}

// ---------------------------------------------------------------------------
// Fused edge kernel: radial MLP (SMEM weights, reg-tiled GEMM) + gather +
// CG tensor product messages + vector red scatter. 64 edges / block.
// ---------------------------------------------------------------------------
#define SME_W1   0
#define SME_W2   512
#define SME_W3   4608
#define SME_HA   25088
#define SME_HB   29184
#define SME_TPW  33280
#define SME_EF   53760
#define SME_Y    54272
#define SME_SND  54528
#define SME_RCV  54592
#define SME_TOT  54656   // floats

template<bool FIRST>
__global__ void __launch_bounds__(256, 1) k_edge(
    const int* __restrict__ ei,
    const float* __restrict__ W1g, const float* __restrict__ W2g,
    const float* __restrict__ W3g, int E_)
{
    extern __shared__ float sm[];
    float* sW1 = sm + SME_W1;
    float* sW2 = sm + SME_W2;
    float* sW3 = sm + SME_W3;
    float* sHa = sm + SME_HA;
    float* sHb = sm + SME_HB;
    float* sTPW = sm + SME_TPW;
    float* sEF = sm + SME_EF;
    float4* sY = (float4*)(sm + SME_Y);
    int* sSend = (int*)(sm + SME_SND);
    int* sRecv = (int*)(sm + SME_RCV);
    const int tid = threadIdx.x;
    constexpr int NB = FIRST ? 2 : 5;
    const float INV_SQRT3 = 0.5773502691896258f;
    const float INV_SQRT2 = 0.7071067811865475f;

    for (int i = tid; i < 512; i += 256) sW1[i] = W1g[i];
    for (int i = tid; i < 4096; i += 256) sW2[i] = W2g[i];
    for (int i = tid; i < 20480; i += 256) sW3[i] = W3g[i];

    long long base = (long long)blockIdx.x * 64;
    if (tid < 64) {
        long long e = base + tid;
        int s = 0, r = -1;
        float4 y = make_float4(0, 0, 0, 0);
        if (e < E_) { s = ei[e]; r = ei[E_ + e]; y = d_Y[e]; }
        sSend[tid] = s;
        sRecv[tid] = r;
        sY[tid] = y;
    }
    if (tid < 128) {
        long long e = base + (tid >> 1);
        float4 v = make_float4(0, 0, 0, 0);
        if (e < E_) v = ((const float4*)d_ef)[e * 2 + (tid & 1)];
        ((float4*)sEF)[tid] = v;
    }
    __syncthreads();

    // Phase B: H1 = silu(EF @ W1)
    #pragma unroll
    for (int i = 0; i < 16; i++) {
        int idx = tid + 256 * i;
        int e = idx >> 6, j = idx & 63;
        float acc = 0.0f;
        #pragma unroll
        for (int k = 0; k < 8; k++) acc += sEF[e * 8 + k] * sW1[k * 64 + j];
        sHa[idx] = silu_f(acc);
    }
    __syncthreads();

    // Phase C: H2 = silu(H1 @ W2), 4x4 micro-tiles with packed f32x2 FMA
    {
        int e0 = (tid >> 4) << 2;
        int j0 = (tid & 15) << 2;
        unsigned long long acc[4][2] = {};
        for (int cc = 0; cc < 64; cc++) {
            const unsigned long long* bp = (const unsigned long long*)&sW2[cc * 64 + j0];
            unsigned long long b0 = bp[0], b1 = bp[1];
            #pragma unroll
            for (int i = 0; i < 4; i++) {
                unsigned long long a2 = pack2(sHa[(e0 + i) * 64 + cc]);
                fma2(acc[i][0], a2, b0);
                fma2(acc[i][1], a2, b1);
            }
        }
        #pragma unroll
        for (int i = 0; i < 4; i++) {
            float2 p0 = unpack2(acc[i][0]);
            float2 p1 = unpack2(acc[i][1]);
            float* dst = &sHb[(e0 + i) * 64 + j0];
            dst[0] = silu_f(p0.x);
            dst[1] = silu_f(p0.y);
            dst[2] = silu_f(p1.x);
            dst[3] = silu_f(p1.y);
        }
    }
    __syncthreads();

    // Phase D: TPW = H2 @ W3, 8 edges x (2*NB) cols per thread, packed FMA.
    // FIRST layer: h1==0 so only paths 0,1 (cols 0..127) are ever consumed.
    {
        int eb = (tid >> 5) << 3;
        int cb = (tid & 31) << 1;
        unsigned long long acc[8][NB];
        #pragma unroll
        for (int ii = 0; ii < 8; ii++)
            #pragma unroll
            for (int i = 0; i < NB; i++) acc[ii][i] = 0ull;
        for (int cc = 0; cc < 64; cc++) {
            unsigned long long a2[8];
            #pragma unroll
            for (int ii = 0; ii < 8; ii++) a2[ii] = pack2(sHb[(eb + ii) * 64 + cc]);
            const float* wrow = &sW3[cc * 320 + cb];
            #pragma unroll
            for (int i = 0; i < NB; i++) {
                unsigned long long b = *(const unsigned long long*)(wrow + 64 * i);
                #pragma unroll
                for (int ii = 0; ii < 8; ii++) fma2(acc[ii][i], a2[ii], b);
            }
        }
        #pragma unroll
        for (int ii = 0; ii < 8; ii++)
            #pragma unroll
            for (int i = 0; i < NB; i++) {
                float2 p = unpack2(acc[ii][i]);
                float* dst = &sTPW[(eb + ii) * 320 + cb + 64 * i];
                dst[0] = p.x;
                dst[1] = p.y;
            }
    }
    __syncthreads();

    // Phase E: gather sender feats, CG tensor product, vector red scatter
    {
        int c = tid & 63;
        int esub = tid >> 6;
        #pragma unroll 1
        for (int g = 0; g < 16; g++) {
            int el = g * 4 + esub;
            int r = sRecv[el];
            if (r >= 0) {
                int s = sSend[el];
                float4 xs = d_x[(size_t)s * CCH + c];
                float4 Yv = sY[el];
                const float* tp = &sTPW[el * 320 + c];
                float t0 = tp[0], t1 = tp[64];
                float m0, m1x, m1y, m1z;
                if (FIRST) {
                    m0 = t0 * xs.x;
                    float t1x0 = t1 * xs.x;
                    m1x = t1x0 * Yv.x;
                    m1y = t1x0 * Yv.y;
                    m1z = t1x0 * Yv.z;
                } else {
                    float t2 = tp[128], t3 = tp[192], t4 = tp[256];
                    float dotv = xs.y * Yv.x + xs.z * Yv.y + xs.w * Yv.z;
                    m0 = t0 * xs.x + t3 * dotv * INV_SQRT3;
                    float cx = xs.z * Yv.z - xs.w * Yv.y;
                    float cy = xs.w * Yv.x - xs.y * Yv.z;
                    float cz = xs.y * Yv.y - xs.z * Yv.x;
                    float t1x0 = t1 * xs.x;
                    float t4s = t4 * INV_SQRT2;
                    m1x = t1x0 * Yv.x + t2 * xs.y + t4s * cx;
                    m1y = t1x0 * Yv.y + t2 * xs.z + t4s * cy;
                    m1z = t1x0 * Yv.z + t2 * xs.w + t4s * cz;
                }
                float* dst = (float*)&d_M[(size_t)r * CCH + c];
                asm volatile("red.global.add.v4.f32 [%0], {%1,%2,%3,%4};"
                             :: "l"(dst), "f"(m0), "f"(m1x), "f"(m1y), "f"(m1z)
                             : "memory");
            }
        }
    }
}

// ---------------------------------------------------------------------------
// Post: M/16 -> linear -> product basis (element weights) -> product linear
// Writes to d_out (float4* out) when out != nullptr, else to d_h.
// ---------------------------------------------------------------------------
#define SMP_LW0 0
#define SMP_LW1 4096
#define SMP_PL0 8192
#define SMP_PL1 12288
#define SMP_PW0 16384
#define SMP_PW1 17152
#define SMP_A   17664
#define SMP_B   18688
#define SMP_TOT 19712   // floats

__global__ void __launch_bounds__(256) k_post(
    const int* __restrict__ species,
    const float* __restrict__ LW0g, const float* __restrict__ LW1g,
    const float* __restrict__ PW0g, const float* __restrict__ PW1g,
    const float* __restrict__ PL0g, const float* __restrict__ PL1g,
    float4* __restrict__ out, int N_)
{
    extern __shared__ float sm[];
    float* sLW0 = sm + SMP_LW0;
    float* sLW1 = sm + SMP_LW1;
    float* sPL0 = sm + SMP_PL0;
    float* sPL1 = sm + SMP_PL1;
    float* sPW0 = sm + SMP_PW0;
    float* sPW1 = sm + SMP_PW1;
    float4* sA = (float4*)(sm + SMP_A);
    float4* sB = (float4*)(sm + SMP_B);
    int tid = threadIdx.x;
    const float INV_SQRT3 = 0.5773502691896258f;
    float4* dsth = (out != nullptr) ? out : d_h;
    for (int i = tid; i < 4096; i += 256) {
        sLW0[i] = LW0g[i];
        sLW1[i] = LW1g[i];
        sPL0[i] = PL0g[i];
        sPL1[i] = PL1g[i];
    }
    for (int i = tid; i < 768; i += 256) sPW0[i] = PW0g[i];
    for (int i = tid; i < 512; i += 256) sPW1[i] = PW1g[i];
    __syncthreads();

    int base = blockIdx.x * 64;
    int c = tid & 63, sub = tid >> 6;
    for (int g = 0; g < 16; g++) {
        int n = base + g * 4 + sub;
        bool act = n < N_;
        if (act) {
            float4 mv = d_M[(size_t)n * CCH + c];
            mv.x *= 0.0625f; mv.y *= 0.0625f; mv.z *= 0.0625f; mv.w *= 0.0625f;
            sA[sub * CCH + c] = mv;
        }
        __syncthreads();
        if (act) {
            float h0 = 0, h1x = 0, h1y = 0, h1z = 0;
            const float4* ar = &sA[sub * CCH];
            #pragma unroll 8
            for (int cc = 0; cc < 64; cc++) {
                float4 a = ar[cc];
                float w0 = sLW0[cc * 64 + c];
                float w1 = sLW1[cc * 64 + c];
                h0 += a.x * w0;
                h1x += a.y * w1;
                h1y += a.z * w1;
                h1z += a.w * w1;
            }
            int sp = species[n];
            float nrm = (h1x * h1x + h1y * h1y + h1z * h1z) * INV_SQRT3;
            const float* p0 = &sPW0[sp * 192 + c];
            float b0 = p0[0] * h0 + p0[64] * h0 * h0 + p0[128] * nrm;
            const float* p1 = &sPW1[sp * 128 + c];
            float q = p1[0] + p1[64] * h0;
            sB[sub * CCH + c] = make_float4(b0, q * h1x, q * h1y, q * h1z);
        }
        __syncthreads();
        if (act) {
            float o0 = 0, o1 = 0, o2 = 0, o3 = 0;
            const float4* br = &sB[sub * CCH];
            #pragma unroll 8
            for (int cc = 0; cc < 64; cc++) {
                float4 b = br[cc];
                float w0 = sPL0[cc * 64 + c];
                float w1 = sPL1[cc * 64 + c];
                o0 += b.x * w0;
                o1 += b.y * w1;
                o2 += b.z * w1;
                o3 += b.w * w1;
            }
            dsth[(size_t)n * CCH + c] = make_float4(o0, o1, o2, o3);
        }
        __syncthreads();
    }
}

// ---------------------------------------------------------------------------
extern "C" void kernel_launch(void* const* d_in, const int* in_sizes, int n_in,
                              void* d_out, int out_size) {
    const float* positions    = (const float*)d_in[0];
    const int*   species      = (const int*)d_in[1];
    const int*   edge_index   = (const int*)d_in[2];
    const float* node_embed_W = (const float*)d_in[3];
    const float* lin_up_W0    = (const float*)d_in[4];
    const float* lin_up_W1    = (const float*)d_in[5];
    const float* mlp_W1       = (const float*)d_in[6];
    const float* mlp_W2       = (const float*)d_in[7];
    const float* mlp_W3       = (const float*)d_in[8];
    const float* lin_W0       = (const float*)d_in[9];
    const float* lin_W1       = (const float*)d_in[10];
    const float* prod_W0      = (const float*)d_in[11];
    const float* prod_W1      = (const float*)d_in[12];
    const float* prod_lin_W0  = (const float*)d_in[13];
    const float* prod_lin_W1  = (const float*)d_in[14];

    int N_ = in_sizes[0] / 3;
    int E_ = in_sizes[2] / 2;

    size_t smemE = (size_t)SME_TOT * 4;
    size_t smemP = (size_t)SMP_TOT * 4;
    cudaFuncSetAttribute(k_edge<true>,  cudaFuncAttributeMaxDynamicSharedMemorySize, (int)smemE);
    cudaFuncSetAttribute(k_edge<false>, cudaFuncAttributeMaxDynamicSharedMemorySize, (int)smemE);
    cudaFuncSetAttribute(k_post,        cudaFuncAttributeMaxDynamicSharedMemorySize, (int)smemP);

    k_geom<<<(E_ + 255) / 256, 256>>>(positions, edge_index, E_);
    k_embed<<<(N_ * CCH + 255) / 256, 256>>>(species, node_embed_W, N_);

    for (int l = 0; l < 2; l++) {
        k_nodeup<<<(N_ + 63) / 64, 256>>>(lin_up_W0 + l * 4096, lin_up_W1 + l * 4096, N_);
        if (l == 0)
            k_edge<true><<<(E_ + 63) / 64, 256, smemE>>>(
                edge_index, mlp_W1, mlp_W2, mlp_W3, E_);
        else
            k_edge<false><<<(E_ + 63) / 64, 256, smemE>>>(
                edge_index, mlp_W1 + 512, mlp_W2 + 4096, mlp_W3 + 20480, E_);
        k_post<<<(N_ + 63) / 64, 256, smemP>>>(
            species, lin_W0 + l * 4096, lin_W1 + l * 4096,
            prod_W0 + l * 768, prod_W1 + l * 512,
            prod_lin_W0 + l * 4096, prod_lin_W1 + l * 4096,
            (l == 1) ? (float4*)d_out : (float4*)nullptr, N_);
    }
}

// round 2
// speedup vs baseline: 1.4070x; 1.4070x over previous
#include <cuda_runtime.h>
#include <cstdint>

#define N_MAX 25000
#define E_MAX 400000
#define CCH 64
#define TILE 128
#define ETHREADS 512
#define EGRID 148

static __device__ float4 d_h[N_MAX * CCH];   // node features [N][C][4] (h0, h1x, h1y, h1z)
static __device__ float4 d_x[N_MAX * CCH];   // up-projected  [N][C][4]
static __device__ float4 d_M[N_MAX * CCH];   // scatter accum [N][C][4]
static __device__ float  d_ef[E_MAX * 8];    // edge bessel feats
static __device__ float4 d_Y[E_MAX];         // sqrt3 * unit vec (w unused)

__device__ __forceinline__ float silu_f(float v) {
    return v / (1.0f + __expf(-v));
}

__device__ __forceinline__ unsigned long long pack2(float x) {
    unsigned long long r;
    asm("mov.b64 %0, {%1, %1};" : "=l"(r) : "f"(x));
    return r;
}
__device__ __forceinline__ void fma2(unsigned long long &d, unsigned long long a, unsigned long long b) {
    asm("fma.rn.f32x2 %0, %1, %2, %0;" : "+l"(d) : "l"(a), "l"(b));
}
__device__ __forceinline__ float2 unpack2(unsigned long long v) {
    float2 r;
    asm("mov.b64 {%0, %1}, %2;" : "=f"(r.x), "=f"(r.y) : "l"(v));
    return r;
}

// ---------------------------------------------------------------------------
// Per-edge geometry: Y1 = sqrt3 * unit vec, bessel radial feats * poly cutoff
// ---------------------------------------------------------------------------
__global__ void k_geom(const float* __restrict__ pos, const int* __restrict__ ei, int E_) {
    int e = blockIdx.x * blockDim.x + threadIdx.x;
    if (e >= E_) return;
    int s = ei[e];
    int r_ = ei[E_ + e];
    float vx = pos[3*s + 0] - pos[3*r_ + 0];
    float vy = pos[3*s + 1] - pos[3*r_ + 1];
    float vz = pos[3*s + 2] - pos[3*r_ + 2];
    float rr = sqrtf(vx*vx + vy*vy + vz*vz);
    rr = fmaxf(rr, 1e-6f);
    float inv_r = 1.0f / rr;
    const float SQRT3 = 1.7320508075688772f;
    float4 Y;
    Y.x = SQRT3 * vx * inv_r;
    Y.y = SQRT3 * vy * inv_r;
    Y.z = SQRT3 * vz * inv_r;
    Y.w = 0.0f;
    d_Y[e] = Y;
    // poly cutoff p=6: 1 - 28x^6 + 48x^7 - 21x^8 for x<1, else 0
    float x = rr * 0.2f;
    float x2 = x * x;
    float x6 = x2 * x2 * x2;
    float fc = 1.0f - 28.0f*x6 + 48.0f*x6*x - 21.0f*x6*x2;
    fc = (x < 1.0f) ? fc : 0.0f;
    const float BC = 0.6324555320336759f;      // sqrt(2/5)
    const float PI_O_R = 0.6283185307179586f;  // pi/5
    float pref = BC * inv_r * fc;
    float ef[8];
    #pragma unroll
    for (int k = 0; k < 8; k++)
        ef[k] = pref * sinf((float)(k + 1) * PI_O_R * rr);
    float4* dst = (float4*)(d_ef + (size_t)e * 8);
    dst[0] = make_float4(ef[0], ef[1], ef[2], ef[3]);
    dst[1] = make_float4(ef[4], ef[5], ef[6], ef[7]);
}

// ---------------------------------------------------------------------------
// h0 init from embedding (one-hot @ W == row select); h1 = 0
// ---------------------------------------------------------------------------
__global__ void k_embed(const int* __restrict__ species, const float* __restrict__ embW, int N_) {
    int idx = blockIdx.x * blockDim.x + threadIdx.x;
    if (idx >= N_ * CCH) return;
    int n = idx >> 6, c = idx & 63;
    int sp = species[n];
    d_h[idx] = make_float4(embW[sp * CCH + c], 0.0f, 0.0f, 0.0f);
}

// ---------------------------------------------------------------------------
// Up-projection: x0 = h0 @ W0, x1 = channel-mix(h1, W1); also zeroes d_M
// ---------------------------------------------------------------------------
__global__ void __launch_bounds__(256) k_nodeup(const float* __restrict__ W0g,
                                                const float* __restrict__ W1g, int N_) {
    __shared__ float sW0[4096];
    __shared__ float sW1[4096];
    __shared__ float4 sH[4 * CCH];
    int tid = threadIdx.x;
    for (int i = tid; i < 4096; i += 256) { sW0[i] = W0g[i]; sW1[i] = W1g[i]; }
    __syncthreads();
    int base = blockIdx.x * 64;
    int c = tid & 63, sub = tid >> 6;
    for (int g = 0; g < 16; g++) {
        int n = base + g * 4 + sub;
        bool act = n < N_;
        if (act) sH[sub * CCH + c] = d_h[(size_t)n * CCH + c];
        __syncthreads();
        if (act) {
            float ax = 0, ay = 0, az = 0, aw = 0;
            const float4* hr = &sH[sub * CCH];
            #pragma unroll 8
            for (int cc = 0; cc < 64; cc++) {
                float4 hv = hr[cc];
                float w0 = sW0[cc * 64 + c];
                float w1 = sW1[cc * 64 + c];
                ax += hv.x * w0;
                ay += hv.y * w1;
                az += hv.z * w1;
                aw += hv.w * w1;
            }
            d_x[(size_t)n * CCH + c] = make_float4(ax, ay, az, aw);
            d_M[(size_t)n * CCH + c] = make_float4(0, 0, 0, 0);
        }
        __syncthreads();
    }
}

// ---------------------------------------------------------------------------
// Persistent fused edge kernel: weights resident in SMEM, loop over 128-edge
// tiles. Radial MLP (B, C) then fused path-weight GEMM + tensor product +
// vector red scatter (D+E) with no TPW staging buffer.
// ---------------------------------------------------------------------------
#define SME_W1   0
#define SME_W2   512
#define SME_W3   4608
#define SME_HA   25088
#define SME_HB   33280
#define SME_EF   41472
#define SME_Y    42496
#define SME_SND  43008
#define SME_RCV  43136
#define SME_TOT  43264   // floats (173 KB)

template<bool FIRST>
__device__ __forceinline__ void emit_msg(float* dst, float4 xs, float4 Yv,
                                         float t0, float t1, float t2,
                                         float t3, float t4) {
    const float INV_SQRT3 = 0.5773502691896258f;
    const float INV_SQRT2 = 0.7071067811865475f;
    float m0, m1x, m1y, m1z;
    if (FIRST) {
        m0 = t0 * xs.x;
        float a = t1 * xs.x;
        m1x = a * Yv.x;
        m1y = a * Yv.y;
        m1z = a * Yv.z;
    } else {
        float dotv = xs.y * Yv.x + xs.z * Yv.y + xs.w * Yv.z;
        m0 = t0 * xs.x + t3 * dotv * INV_SQRT3;
        float cx = xs.z * Yv.z - xs.w * Yv.y;
        float cy = xs.w * Yv.x - xs.y * Yv.z;
        float cz = xs.y * Yv.y - xs.z * Yv.x;
        float a = t1 * xs.x;
        float t4s = t4 * INV_SQRT2;
        m1x = a * Yv.x + t2 * xs.y + t4s * cx;
        m1y = a * Yv.y + t2 * xs.z + t4s * cy;
        m1z = a * Yv.z + t2 * xs.w + t4s * cz;
    }
    asm volatile("red.global.add.v4.f32 [%0], {%1,%2,%3,%4};"
                 :: "l"(dst), "f"(m0), "f"(m1x), "f"(m1y), "f"(m1z)
                 : "memory");
}

template<bool FIRST>
__global__ void __launch_bounds__(ETHREADS, 1) k_edge(
    const int* __restrict__ ei,
    const float* __restrict__ W1g, const float* __restrict__ W2g,
    const float* __restrict__ W3g, int E_)
{
    extern __shared__ float sm[];
    float* sW1 = sm + SME_W1;
    float* sW2 = sm + SME_W2;
    float* sW3 = sm + SME_W3;
    float* sHa = sm + SME_HA;
    float* sHb = sm + SME_HB;
    float* sEF = sm + SME_EF;
    float4* sY = (float4*)(sm + SME_Y);
    int* sSend = (int*)(sm + SME_SND);
    int* sRecv = (int*)(sm + SME_RCV);
    const int tid = threadIdx.x;
    constexpr int NB = FIRST ? 2 : 5;

    // one-time weight load (persistent block)
    for (int i = tid; i < 512; i += ETHREADS) sW1[i] = W1g[i];
    for (int i = tid; i < 4096; i += ETHREADS) sW2[i] = W2g[i];
    for (int i = tid; i < 20480; i += ETHREADS) sW3[i] = W3g[i];

    int nTiles = (E_ + TILE - 1) / TILE;
    for (int t = blockIdx.x; t < nTiles; t += gridDim.x) {
        long long base = (long long)t * TILE;
        __syncthreads();   // weights ready (iter 0) / prev tile consumers done
        if (tid < 256) {
            long long e = base + (tid >> 1);
            float4 v = make_float4(0, 0, 0, 0);
            if (e < E_) v = ((const float4*)d_ef)[e * 2 + (tid & 1)];
            ((float4*)sEF)[tid] = v;
        } else if (tid < 384) {
            int i = tid - 256;
            long long e = base + i;
            float4 y = make_float4(0, 0, 0, 0);
            if (e < E_) y = d_Y[e];
            sY[i] = y;
        } else {
            int i = tid - 384;
            long long e = base + i;
            int s = 0, r = -1;
            if (e < E_) { s = ei[e]; r = ei[E_ + e]; }
            sSend[i] = s;
            sRecv[i] = r;
        }
        __syncthreads();

        // Phase B: H1 = silu(EF @ W1)   [128x8]@[8x64]
        #pragma unroll
        for (int i = 0; i < (TILE * 64) / ETHREADS; i++) {
            int idx = tid + ETHREADS * i;
            int e = idx >> 6, j = idx & 63;
            float acc = 0.0f;
            #pragma unroll
            for (int k = 0; k < 8; k++) acc += sEF[e * 8 + k] * sW1[k * 64 + j];
            sHa[idx] = silu_f(acc);
        }
        __syncthreads();

        // Phase C: H2 = silu(H1 @ W2)   [128x64]@[64x64], 4 edges x 4 cols
        {
            int e0 = (tid >> 4) << 2;
            int j0 = (tid & 15) << 2;
            unsigned long long acc[4][2] = {};
            #pragma unroll 4
            for (int cc = 0; cc < 64; cc++) {
                const unsigned long long* bp = (const unsigned long long*)&sW2[cc * 64 + j0];
                unsigned long long b0 = bp[0], b1 = bp[1];
                #pragma unroll
                for (int i = 0; i < 4; i++) {
                    unsigned long long a2 = pack2(sHa[(e0 + i) * 64 + cc]);
                    fma2(acc[i][0], a2, b0);
                    fma2(acc[i][1], a2, b1);
                }
            }
            #pragma unroll
            for (int i = 0; i < 4; i++) {
                float2 p0 = unpack2(acc[i][0]);
                float2 p1 = unpack2(acc[i][1]);
                float* dst = &sHb[(e0 + i) * 64 + j0];
                dst[0] = silu_f(p0.x);
                dst[1] = silu_f(p0.y);
                dst[2] = silu_f(p1.x);
                dst[3] = silu_f(p1.y);
            }
        }
        __syncthreads();

        // Phase D+E fused: TPW = H2 @ W3 then tensor product + red scatter.
        // Thread tile: 8 edges x 2 channels x NB paths (acc stays in regs).
        {
            int eb = (tid >> 5) << 3;
            int cb = (tid & 31) << 1;
            unsigned long long acc[8][NB];
            #pragma unroll
            for (int ii = 0; ii < 8; ii++)
                #pragma unroll
                for (int p = 0; p < NB; p++) acc[ii][p] = 0ull;

            #pragma unroll 2
            for (int cc = 0; cc < 64; cc++) {
                unsigned long long a2[8];
                #pragma unroll
                for (int ii = 0; ii < 8; ii++) a2[ii] = pack2(sHb[(eb + ii) * 64 + cc]);
                const float* wrow = &sW3[cc * 320 + cb];
                #pragma unroll
                for (int p = 0; p < NB; p++) {
                    unsigned long long b = *(const unsigned long long*)(wrow + 64 * p);
                    #pragma unroll
                    for (int ii = 0; ii < 8; ii++) fma2(acc[ii][p], a2[ii], b);
                }
            }

            // epilogue: per edge, per channel-pair, build messages + scatter
            #pragma unroll 1
            for (int ii = 0; ii < 8; ii++) {
                int el = eb + ii;
                int r = sRecv[el];
                if (r < 0) continue;
                int s = sSend[el];
                float4 Yv = sY[el];
                const float4* xp = &d_x[(size_t)s * CCH + cb];
                float4 xs0 = xp[0];
                float4 xs1 = xp[1];
                float2 t0 = unpack2(acc[ii][0]);
                float2 t1 = unpack2(acc[ii][1]);
                float2 t2 = make_float2(0, 0), t3 = make_float2(0, 0), t4 = make_float2(0, 0);
                if (!FIRST) {
                    t2 = unpack2(acc[ii][2]);
                    t3 = unpack2(acc[ii][3]);
                    t4 = unpack2(acc[ii][4]);
                }
                float* dst = (float*)&d_M[(size_t)r * CCH + cb];
                emit_msg<FIRST>(dst,     xs0, Yv, t0.x, t1.x, t2.x, t3.x, t4.x);
                emit_msg<FIRST>(dst + 4, xs1, Yv, t0.y, t1.y, t2.y, t3.y, t4.y);
            }
        }
    }
}

// ---------------------------------------------------------------------------
// Post: M/16 -> linear -> product basis (element weights) -> product linear
// Writes to d_out (float4* out) when out != nullptr, else to d_h.
// ---------------------------------------------------------------------------
#define SMP_LW0 0
#define SMP_LW1 4096
#define SMP_PL0 8192
#define SMP_PL1 12288
#define SMP_PW0 16384
#define SMP_PW1 17152
#define SMP_A   17664
#define SMP_B   18688
#define SMP_TOT 19712   // floats

__global__ void __launch_bounds__(256) k_post(
    const int* __restrict__ species,
    const float* __restrict__ LW0g, const float* __restrict__ LW1g,
    const float* __restrict__ PW0g, const float* __restrict__ PW1g,
    const float* __restrict__ PL0g, const float* __restrict__ PL1g,
    float4* __restrict__ out, int N_)
{
    extern __shared__ float sm[];
    float* sLW0 = sm + SMP_LW0;
    float* sLW1 = sm + SMP_LW1;
    float* sPL0 = sm + SMP_PL0;
    float* sPL1 = sm + SMP_PL1;
    float* sPW0 = sm + SMP_PW0;
    float* sPW1 = sm + SMP_PW1;
    float4* sA = (float4*)(sm + SMP_A);
    float4* sB = (float4*)(sm + SMP_B);
    int tid = threadIdx.x;
    const float INV_SQRT3 = 0.5773502691896258f;
    float4* dsth = (out != nullptr) ? out : d_h;
    for (int i = tid; i < 4096; i += 256) {
        sLW0[i] = LW0g[i];
        sLW1[i] = LW1g[i];
        sPL0[i] = PL0g[i];
        sPL1[i] = PL1g[i];
    }
    for (int i = tid; i < 768; i += 256) sPW0[i] = PW0g[i];
    for (int i = tid; i < 512; i += 256) sPW1[i] = PW1g[i];
    __syncthreads();

    int base = blockIdx.x * 64;
    int c = tid & 63, sub = tid >> 6;
    for (int g = 0; g < 16; g++) {
        int n = base + g * 4 + sub;
        bool act = n < N_;
        if (act) {
            float4 mv = d_M[(size_t)n * CCH + c];
            mv.x *= 0.0625f; mv.y *= 0.0625f; mv.z *= 0.0625f; mv.w *= 0.0625f;
            sA[sub * CCH + c] = mv;
        }
        __syncthreads();
        if (act) {
            float h0 = 0, h1x = 0, h1y = 0, h1z = 0;
            const float4* ar = &sA[sub * CCH];
            #pragma unroll 8
            for (int cc = 0; cc < 64; cc++) {
                float4 a = ar[cc];
                float w0 = sLW0[cc * 64 + c];
                float w1 = sLW1[cc * 64 + c];
                h0 += a.x * w0;
                h1x += a.y * w1;
                h1y += a.z * w1;
                h1z += a.w * w1;
            }
            int sp = species[n];
            float nrm = (h1x * h1x + h1y * h1y + h1z * h1z) * INV_SQRT3;
            const float* p0 = &sPW0[sp * 192 + c];
            float b0 = p0[0] * h0 + p0[64] * h0 * h0 + p0[128] * nrm;
            const float* p1 = &sPW1[sp * 128 + c];
            float q = p1[0] + p1[64] * h0;
            sB[sub * CCH + c] = make_float4(b0, q * h1x, q * h1y, q * h1z);
        }
        __syncthreads();
        if (act) {
            float o0 = 0, o1 = 0, o2 = 0, o3 = 0;
            const float4* br = &sB[sub * CCH];
            #pragma unroll 8
            for (int cc = 0; cc < 64; cc++) {
                float4 b = br[cc];
                float w0 = sPL0[cc * 64 + c];
                float w1 = sPL1[cc * 64 + c];
                o0 += b.x * w0;
                o1 += b.y * w1;
                o2 += b.z * w1;
                o3 += b.w * w1;
            }
            dsth[(size_t)n * CCH + c] = make_float4(o0, o1, o2, o3);
        }
        __syncthreads();
    }
}

// ---------------------------------------------------------------------------
extern "C" void kernel_launch(void* const* d_in, const int* in_sizes, int n_in,
                              void* d_out, int out_size) {
    const float* positions    = (const float*)d_in[0];
    const int*   species      = (const int*)d_in[1];
    const int*   edge_index   = (const int*)d_in[2];
    const float* node_embed_W = (const float*)d_in[3];
    const float* lin_up_W0    = (const float*)d_in[4];
    const float* lin_up_W1    = (const float*)d_in[5];
    const float* mlp_W1       = (const float*)d_in[6];
    const float* mlp_W2       = (const float*)d_in[7];
    const float* mlp_W3       = (const float*)d_in[8];
    const float* lin_W0       = (const float*)d_in[9];
    const float* lin_W1       = (const float*)d_in[10];
    const float* prod_W0      = (const float*)d_in[11];
    const float* prod_W1      = (const float*)d_in[12];
    const float* prod_lin_W0  = (const float*)d_in[13];
    const float* prod_lin_W1  = (const float*)d_in[14];

    int N_ = in_sizes[0] / 3;
    int E_ = in_sizes[2] / 2;

    size_t smemE = (size_t)SME_TOT * 4;
    size_t smemP = (size_t)SMP_TOT * 4;
    cudaFuncSetAttribute(k_edge<true>,  cudaFuncAttributeMaxDynamicSharedMemorySize, (int)smemE);
    cudaFuncSetAttribute(k_edge<false>, cudaFuncAttributeMaxDynamicSharedMemorySize, (int)smemE);
    cudaFuncSetAttribute(k_post,        cudaFuncAttributeMaxDynamicSharedMemorySize, (int)smemP);

    k_geom<<<(E_ + 255) / 256, 256>>>(positions, edge_index, E_);
    k_embed<<<(N_ * CCH + 255) / 256, 256>>>(species, node_embed_W, N_);

    for (int l = 0; l < 2; l++) {
        k_nodeup<<<(N_ + 63) / 64, 256>>>(lin_up_W0 + l * 4096, lin_up_W1 + l * 4096, N_);
        if (l == 0)
            k_edge<true><<<EGRID, ETHREADS, smemE>>>(
                edge_index, mlp_W1, mlp_W2, mlp_W3, E_);
        else
            k_edge<false><<<EGRID, ETHREADS, smemE>>>(
                edge_index, mlp_W1 + 512, mlp_W2 + 4096, mlp_W3 + 20480, E_);
        k_post<<<(N_ + 63) / 64, 256, smemP>>>(
            species, lin_W0 + l * 4096, lin_W1 + l * 4096,
            prod_W0 + l * 768, prod_W1 + l * 512,
            prod_lin_W0 + l * 4096, prod_lin_W1 + l * 4096,
            (l == 1) ? (float4*)d_out : (float4*)nullptr, N_);
    }
}

// round 4
// speedup vs baseline: 1.5178x; 1.0788x over previous
#include <cuda_runtime.h>
#include <cstdint>

#define N_MAX 25000
#define E_MAX 400000
#define CCH 64
#define TILE 128
#define ETHREADS 1024
#define EGRID 148

static __device__ float4 d_x[N_MAX * CCH];   // up-projected  [N][C][4]
static __device__ float4 d_M[N_MAX * CCH];   // scatter accum [N][C][4]
static __device__ float  d_ef[E_MAX * 8];    // edge bessel feats
static __device__ float4 d_Y[E_MAX];         // sqrt3 * unit vec (w unused)
static __device__ float  d_U[4 * CCH];       // embW @ lin_up_W0[0]  (layer-0 x0 rows)
static __device__ float  d_W0c[CCH * CCH];   // prod_lin_W0[0] @ lin_up_W0[1]
static __device__ float  d_W1c[CCH * CCH];   // prod_lin_W1[0] @ lin_up_W1[1]

__device__ __forceinline__ float silu_f(float v) {
    return v / (1.0f + __expf(-v));
}

__device__ __forceinline__ unsigned long long pack2(float x) {
    unsigned long long r;
    asm("mov.b64 %0, {%1, %1};" : "=l"(r) : "f"(x));
    return r;
}
__device__ __forceinline__ void fma2(unsigned long long &d, unsigned long long a, unsigned long long b) {
    asm("fma.rn.f32x2 %0, %1, %2, %0;" : "+l"(d) : "l"(a), "l"(b));
}
__device__ __forceinline__ float2 unpack2(unsigned long long v) {
    float2 r;
    asm("mov.b64 {%0, %1}, %2;" : "=f"(r.x), "=f"(r.y) : "l"(v));
    return r;
}

// ---------------------------------------------------------------------------
// Per-edge geometry (accurate sinf — MUFU __sinf is NOT accurate at 8pi)
// ---------------------------------------------------------------------------
__global__ void k_geom(const float* __restrict__ pos, const int* __restrict__ ei, int E_) {
    int e = blockIdx.x * blockDim.x + threadIdx.x;
    if (e >= E_) return;
    int s = ei[e];
    int r_ = ei[E_ + e];
    float vx = pos[3*s + 0] - pos[3*r_ + 0];
    float vy = pos[3*s + 1] - pos[3*r_ + 1];
    float vz = pos[3*s + 2] - pos[3*r_ + 2];
    float rr = sqrtf(vx*vx + vy*vy + vz*vz);
    rr = fmaxf(rr, 1e-6f);
    float inv_r = 1.0f / rr;
    const float SQRT3 = 1.7320508075688772f;
    float4 Y;
    Y.x = SQRT3 * vx * inv_r;
    Y.y = SQRT3 * vy * inv_r;
    Y.z = SQRT3 * vz * inv_r;
    Y.w = 0.0f;
    d_Y[e] = Y;
    float x = rr * 0.2f;
    float x2 = x * x;
    float x6 = x2 * x2 * x2;
    float fc = 1.0f - 28.0f*x6 + 48.0f*x6*x - 21.0f*x6*x2;
    fc = (x < 1.0f) ? fc : 0.0f;
    const float BC = 0.6324555320336759f;      // sqrt(2/5)
    const float PI_O_R = 0.6283185307179586f;  // pi/5
    float pref = BC * inv_r * fc;
    float ef[8];
    #pragma unroll
    for (int k = 0; k < 8; k++)
        ef[k] = pref * sinf((float)(k + 1) * PI_O_R * rr);
    float4* dst = (float4*)(d_ef + (size_t)e * 8);
    dst[0] = make_float4(ef[0], ef[1], ef[2], ef[3]);
    dst[1] = make_float4(ef[4], ef[5], ef[6], ef[7]);
}

// ---------------------------------------------------------------------------
// Weight prep (single block): U = embW @ LU0_l0;  W0c = PL0_l0 @ LU0_l1;
// W1c = PL1_l0 @ LU1_l1
// ---------------------------------------------------------------------------
__global__ void __launch_bounds__(256) k_prepw(
    const float* __restrict__ embW, const float* __restrict__ LU0_l0,
    const float* __restrict__ PL0_l0, const float* __restrict__ LU0_l1,
    const float* __restrict__ PL1_l0, const float* __restrict__ LU1_l1)
{
    int tid = threadIdx.x;
    // U: [4 x 64]
    {
        int s = tid >> 6, j = tid & 63;
        float acc = 0.0f;
        for (int k = 0; k < 64; k++) acc += embW[s * 64 + k] * LU0_l0[k * 64 + j];
        d_U[tid] = acc;
    }
    // W0c, W1c: [64 x 64]
    for (int t = tid; t < 4096; t += 256) {
        int i = t >> 6, j = t & 63;
        float a0 = 0.0f, a1 = 0.0f;
        for (int k = 0; k < 64; k++) {
            a0 += PL0_l0[i * 64 + k] * LU0_l1[k * 64 + j];
            a1 += PL1_l0[i * 64 + k] * LU1_l1[k * 64 + j];
        }
        d_W0c[t] = a0;
        d_W1c[t] = a1;
    }
}

// ---------------------------------------------------------------------------
// Layer-0 seed: x = row-select of U (h1 == 0), zero M
// ---------------------------------------------------------------------------
__global__ void k_seed(const int* __restrict__ species, int N_) {
    int idx = blockIdx.x * blockDim.x + threadIdx.x;
    if (idx >= N_ * CCH) return;
    int n = idx >> 6, c = idx & 63;
    int sp = species[n];
    d_x[idx] = make_float4(d_U[sp * CCH + c], 0.0f, 0.0f, 0.0f);
    d_M[idx] = make_float4(0, 0, 0, 0);
}

// ---------------------------------------------------------------------------
// Persistent fused edge kernel (1024 threads, 32 warps): SMEM-resident
// weights, 128-edge tiles, fused MLP + tensor product + red scatter.
// ---------------------------------------------------------------------------
#define SME_W1   0
#define SME_W2   512
#define SME_W3   4608
#define SME_HA   25088
#define SME_HB   33280
#define SME_EF   41472
#define SME_Y    42496
#define SME_SND  43008
#define SME_RCV  43136
#define SME_TOT  43264   // floats (169 KB)

template<bool FIRST>
__device__ __forceinline__ void emit_msg(float* dst, float4 xs, float4 Yv,
                                         float t0, float t1, float t2,
                                         float t3, float t4) {
    const float INV_SQRT3 = 0.5773502691896258f;
    const float INV_SQRT2 = 0.7071067811865475f;
    float m0, m1x, m1y, m1z;
    if (FIRST) {
        m0 = t0 * xs.x;
        float a = t1 * xs.x;
        m1x = a * Yv.x;
        m1y = a * Yv.y;
        m1z = a * Yv.z;
    } else {
        float dotv = xs.y * Yv.x + xs.z * Yv.y + xs.w * Yv.z;
        m0 = t0 * xs.x + t3 * dotv * INV_SQRT3;
        float cx = xs.z * Yv.z - xs.w * Yv.y;
        float cy = xs.w * Yv.x - xs.y * Yv.z;
        float cz = xs.y * Yv.y - xs.z * Yv.x;
        float a = t1 * xs.x;
        float t4s = t4 * INV_SQRT2;
        m1x = a * Yv.x + t2 * xs.y + t4s * cx;
        m1y = a * Yv.y + t2 * xs.z + t4s * cy;
        m1z = a * Yv.z + t2 * xs.w + t4s * cz;
    }
    asm volatile("red.global.add.v4.f32 [%0], {%1,%2,%3,%4};"
                 :: "l"(dst), "f"(m0), "f"(m1x), "f"(m1y), "f"(m1z)
                 : "memory");
}

template<bool FIRST>
__global__ void __launch_bounds__(ETHREADS, 1) k_edge(
    const int* __restrict__ ei,
    const float* __restrict__ W1g, const float* __restrict__ W2g,
    const float* __restrict__ W3g, int E_)
{
    extern __shared__ float sm[];
    float* sW1 = sm + SME_W1;
    float* sW2 = sm + SME_W2;
    float* sW3 = sm + SME_W3;
    float* sHa = sm + SME_HA;
    float* sHb = sm + SME_HB;
    float* sEF = sm + SME_EF;
    float4* sY = (float4*)(sm + SME_Y);
    int* sSend = (int*)(sm + SME_SND);
    int* sRecv = (int*)(sm + SME_RCV);
    const int tid = threadIdx.x;
    constexpr int NB = FIRST ? 2 : 5;

    // one-time weight load (persistent block)
    for (int i = tid; i < 512; i += ETHREADS) sW1[i] = W1g[i];
    for (int i = tid; i < 4096; i += ETHREADS) sW2[i] = W2g[i];
    for (int i = tid; i < 20480; i += ETHREADS) sW3[i] = W3g[i];

    int nTiles = (E_ + TILE - 1) / TILE;
    for (int t = blockIdx.x; t < nTiles; t += gridDim.x) {
        long long base = (long long)t * TILE;
        __syncthreads();   // weights ready (iter 0) / prev tile consumers done
        if (tid < 256) {
            long long e = base + (tid >> 1);
            float4 v = make_float4(0, 0, 0, 0);
            if (e < E_) v = ((const float4*)d_ef)[e * 2 + (tid & 1)];
            ((float4*)sEF)[tid] = v;
        } else if (tid < 384) {
            int i = tid - 256;
            long long e = base + i;
            float4 y = make_float4(0, 0, 0, 0);
            if (e < E_) y = d_Y[e];
            sY[i] = y;
        } else if (tid < 512) {
            int i = tid - 384;
            long long e = base + i;
            int s = 0, r = -1;
            if (e < E_) { s = ei[e]; r = ei[E_ + e]; }
            sSend[i] = s;
            sRecv[i] = r;
        }
        __syncthreads();

        // Phase B: H1 = silu(EF @ W1)   [128x8]@[8x64]
        #pragma unroll
        for (int i = 0; i < (TILE * 64) / ETHREADS; i++) {
            int idx = tid + ETHREADS * i;
            int e = idx >> 6, j = idx & 63;
            float acc = 0.0f;
            #pragma unroll
            for (int k = 0; k < 8; k++) acc += sEF[e * 8 + k] * sW1[k * 64 + j];
            sHa[idx] = silu_f(acc);
        }
        __syncthreads();

        // Phase C: H2 = silu(H1 @ W2)  [128x64]@[64x64], 2 edges x 4 cols
        {
            int e0 = (tid >> 4) << 1;
            int j0 = (tid & 15) << 2;
            unsigned long long acc[2][2] = {};
            #pragma unroll 4
            for (int cc = 0; cc < 64; cc++) {
                const unsigned long long* bp = (const unsigned long long*)&sW2[cc * 64 + j0];
                unsigned long long b0 = bp[0], b1 = bp[1];
                #pragma unroll
                for (int i = 0; i < 2; i++) {
                    unsigned long long a2 = pack2(sHa[(e0 + i) * 64 + cc]);
                    fma2(acc[i][0], a2, b0);
                    fma2(acc[i][1], a2, b1);
                }
            }
            #pragma unroll
            for (int i = 0; i < 2; i++) {
                float2 p0 = unpack2(acc[i][0]);
                float2 p1 = unpack2(acc[i][1]);
                float* dst = &sHb[(e0 + i) * 64 + j0];
                dst[0] = silu_f(p0.x);
                dst[1] = silu_f(p0.y);
                dst[2] = silu_f(p1.x);
                dst[3] = silu_f(p1.y);
            }
        }
        __syncthreads();

        // Phase D+E fused: TPW = H2 @ W3 then tensor product + red scatter.
        // Thread tile: 4 edges x 2 channels x NB paths.
        {
            int eb = (tid >> 5) << 2;
            int cb = (tid & 31) << 1;
            unsigned long long acc[4][NB];
            #pragma unroll
            for (int ii = 0; ii < 4; ii++)
                #pragma unroll
                for (int p = 0; p < NB; p++) acc[ii][p] = 0ull;

            #pragma unroll 2
            for (int cc = 0; cc < 64; cc++) {
                unsigned long long a2[4];
                #pragma unroll
                for (int ii = 0; ii < 4; ii++) a2[ii] = pack2(sHb[(eb + ii) * 64 + cc]);
                const float* wrow = &sW3[cc * 320 + cb];
                #pragma unroll
                for (int p = 0; p < NB; p++) {
                    unsigned long long b = *(const unsigned long long*)(wrow + 64 * p);
                    #pragma unroll
                    for (int ii = 0; ii < 4; ii++) fma2(acc[ii][p], a2[ii], b);
                }
            }

            // epilogue: per edge, per channel-pair, build messages + scatter
            #pragma unroll 1
            for (int ii = 0; ii < 4; ii++) {
                int el = eb + ii;
                int r = sRecv[el];
                if (r < 0) continue;
                int s = sSend[el];
                float4 Yv = sY[el];
                const float4* xp = &d_x[(size_t)s * CCH + cb];
                float4 xs0 = xp[0];
                float4 xs1 = xp[1];
                float2 t0 = unpack2(acc[ii][0]);
                float2 t1 = unpack2(acc[ii][1]);
                float2 t2 = make_float2(0, 0), t3 = make_float2(0, 0), t4 = make_float2(0, 0);
                if (!FIRST) {
                    t2 = unpack2(acc[ii][2]);
                    t3 = unpack2(acc[ii][3]);
                    t4 = unpack2(acc[ii][4]);
                }
                float* dst = (float*)&d_M[(size_t)r * CCH + cb];
                emit_msg<FIRST>(dst,     xs0, Yv, t0.x, t1.x, t2.x, t3.x, t4.x);
                emit_msg<FIRST>(dst + 4, xs1, Yv, t0.y, t1.y, t2.y, t3.y, t4.y);
            }
        }
    }
}

// ---------------------------------------------------------------------------
// Fused post(l0)+up(l1): M/16 -> lin -> product basis -> combined lin ->
// writes d_x for layer 1 and zeroes d_M.  FINAL=true variant writes out.
// ---------------------------------------------------------------------------
#define SMP_LW0 0
#define SMP_LW1 4096
#define SMP_PL0 8192
#define SMP_PL1 12288
#define SMP_PW0 16384
#define SMP_PW1 17152
#define SMP_A   17664
#define SMP_B   18688
#define SMP_TOT 19712   // floats

template<bool FINAL>
__global__ void __launch_bounds__(256) k_post(
    const int* __restrict__ species,
    const float* __restrict__ LW0g, const float* __restrict__ LW1g,
    const float* __restrict__ PW0g, const float* __restrict__ PW1g,
    const float* __restrict__ PL0g, const float* __restrict__ PL1g,
    float4* __restrict__ out, int N_)
{
    extern __shared__ float sm[];
    float* sLW0 = sm + SMP_LW0;
    float* sLW1 = sm + SMP_LW1;
    float* sPL0 = sm + SMP_PL0;
    float* sPL1 = sm + SMP_PL1;
    float* sPW0 = sm + SMP_PW0;
    float* sPW1 = sm + SMP_PW1;
    float4* sA = (float4*)(sm + SMP_A);
    float4* sB = (float4*)(sm + SMP_B);
    int tid = threadIdx.x;
    const float INV_SQRT3 = 0.5773502691896258f;
    for (int i = tid; i < 4096; i += 256) {
        sLW0[i] = LW0g[i];
        sLW1[i] = LW1g[i];
        sPL0[i] = PL0g[i];
        sPL1[i] = PL1g[i];
    }
    for (int i = tid; i < 768; i += 256) sPW0[i] = PW0g[i];
    for (int i = tid; i < 512; i += 256) sPW1[i] = PW1g[i];
    __syncthreads();

    int base = blockIdx.x * 64;
    int c = tid & 63, sub = tid >> 6;
    for (int g = 0; g < 16; g++) {
        int n = base + g * 4 + sub;
        bool act = n < N_;
        if (act) {
            float4 mv = d_M[(size_t)n * CCH + c];
            mv.x *= 0.0625f; mv.y *= 0.0625f; mv.z *= 0.0625f; mv.w *= 0.0625f;
            sA[sub * CCH + c] = mv;
        }
        __syncthreads();
        if (act) {
            float h0 = 0, h1x = 0, h1y = 0, h1z = 0;
            const float4* ar = &sA[sub * CCH];
            #pragma unroll 8
            for (int cc = 0; cc < 64; cc++) {
                float4 a = ar[cc];
                float w0 = sLW0[cc * 64 + c];
                float w1 = sLW1[cc * 64 + c];
                h0 += a.x * w0;
                h1x += a.y * w1;
                h1y += a.z * w1;
                h1z += a.w * w1;
            }
            int sp = species[n];
            float nrm = (h1x * h1x + h1y * h1y + h1z * h1z) * INV_SQRT3;
            const float* p0 = &sPW0[sp * 192 + c];
            float b0 = p0[0] * h0 + p0[64] * h0 * h0 + p0[128] * nrm;
            const float* p1 = &sPW1[sp * 128 + c];
            float q = p1[0] + p1[64] * h0;
            sB[sub * CCH + c] = make_float4(b0, q * h1x, q * h1y, q * h1z);
        }
        __syncthreads();
        if (act) {
            float o0 = 0, o1 = 0, o2 = 0, o3 = 0;
            const float4* br = &sB[sub * CCH];
            #pragma unroll 8
            for (int cc = 0; cc < 64; cc++) {
                float4 b = br[cc];
                float w0 = sPL0[cc * 64 + c];
                float w1 = sPL1[cc * 64 + c];
                o0 += b.x * w0;
                o1 += b.y * w1;
                o2 += b.z * w1;
                o3 += b.w * w1;
            }
            if (FINAL) {
                out[(size_t)n * CCH + c] = make_float4(o0, o1, o2, o3);
            } else {
                d_x[(size_t)n * CCH + c] = make_float4(o0, o1, o2, o3);
                d_M[(size_t)n * CCH + c] = make_float4(0, 0, 0, 0);
            }
        }
        __syncthreads();
    }
}

// ---------------------------------------------------------------------------
extern "C" void kernel_launch(void* const* d_in, const int* in_sizes, int n_in,
                              void* d_out, int out_size) {
    const float* positions    = (const float*)d_in[0];
    const int*   species      = (const int*)d_in[1];
    const int*   edge_index   = (const int*)d_in[2];
    const float* node_embed_W = (const float*)d_in[3];
    const float* lin_up_W0    = (const float*)d_in[4];
    const float* lin_up_W1    = (const float*)d_in[5];
    const float* mlp_W1       = (const float*)d_in[6];
    const float* mlp_W2       = (const float*)d_in[7];
    const float* mlp_W3       = (const float*)d_in[8];
    const float* lin_W0       = (const float*)d_in[9];
    const float* lin_W1       = (const float*)d_in[10];
    const float* prod_W0      = (const float*)d_in[11];
    const float* prod_W1      = (const float*)d_in[12];
    const float* prod_lin_W0  = (const float*)d_in[13];
    const float* prod_lin_W1  = (const float*)d_in[14];

    int N_ = in_sizes[0] / 3;
    int E_ = in_sizes[2] / 2;

    size_t smemE = (size_t)SME_TOT * 4;
    size_t smemP = (size_t)SMP_TOT * 4;
    cudaFuncSetAttribute(k_edge<true>,  cudaFuncAttributeMaxDynamicSharedMemorySize, (int)smemE);
    cudaFuncSetAttribute(k_edge<false>, cudaFuncAttributeMaxDynamicSharedMemorySize, (int)smemE);
    cudaFuncSetAttribute(k_post<true>,  cudaFuncAttributeMaxDynamicSharedMemorySize, (int)smemP);
    cudaFuncSetAttribute(k_post<false>, cudaFuncAttributeMaxDynamicSharedMemorySize, (int)smemP);

    k_geom<<<(E_ + 255) / 256, 256>>>(positions, edge_index, E_);
    k_prepw<<<1, 256>>>(node_embed_W, lin_up_W0,
                        prod_lin_W0, lin_up_W0 + 4096,
                        prod_lin_W1, lin_up_W1 + 4096);
    k_seed<<<(N_ * CCH + 255) / 256, 256>>>(species, N_);

    void* p0;
    void* p1;
    cudaGetSymbolAddress(&p0, d_W0c);
    cudaGetSymbolAddress(&p1, d_W1c);
    const float* W0c_sym = (const float*)p0;
    const float* W1c_sym = (const float*)p1;

    // layer 0
    k_edge<true><<<EGRID, ETHREADS, smemE>>>(edge_index, mlp_W1, mlp_W2, mlp_W3, E_);
    // fused post(l0) + up(l1): final GEMM uses combined weights, writes d_x
    k_post<false><<<(N_ + 63) / 64, 256, smemP>>>(
        species, lin_W0, lin_W1, prod_W0, prod_W1,
        W0c_sym, W1c_sym, nullptr, N_);

    // layer 1
    k_edge<false><<<EGRID, ETHREADS, smemE>>>(
        edge_index, mlp_W1 + 512, mlp_W2 + 4096, mlp_W3 + 20480, E_);
    k_post<true><<<(N_ + 63) / 64, 256, smemP>>>(
        species, lin_W0 + 4096, lin_W1 + 4096,
        prod_W0 + 768, prod_W1 + 512,
        prod_lin_W0 + 4096, prod_lin_W1 + 4096,
        (float4*)d_out, N_);
}